// round 12
// baseline (speedup 1.0000x reference)
#include <cuda_runtime.h>
#include <cuda_bf16.h>
#include <cstdint>

#define SEQL  256
#define BATCHN 64
#define EMBD  256
#define HID   512
#define OUTD  18
#define MROWS (SEQL*BATCHN)   // 16384

typedef unsigned long long u64;

// ---------------- packed f32x2 helpers ----------------
__device__ __forceinline__ u64 ffma2(u64 a, u64 b, u64 c) {
    u64 d; asm("fma.rn.f32x2 %0, %1, %2, %3;" : "=l"(d) : "l"(a), "l"(b), "l"(c));
    return d;
}
__device__ __forceinline__ u64 pack2(float lo, float hi) {
    u64 r; asm("mov.b64 %0, {%1, %2};" : "=l"(r) : "f"(lo), "f"(hi));
    return r;
}
__device__ __forceinline__ float2 unpk2(u64 v) {
    float lo, hi; asm("mov.b64 {%0, %1}, %2;" : "=f"(lo), "=f"(hi) : "l"(v));
    return make_float2(lo, hi);
}

// ---------------- scratch (static device arrays; no allocation) ----------------
__device__ float g_emfcT[EMBD * EMBD];                // 256 KB  emfc_w^T
__device__ float g_M    [2 * HID * EMBD];             // 1 MB    fused W  [1024,256]
__device__ float g_bf   [2 * HID];                    // fused bias [1024]
__device__ float g_xp0[2 * SEQL * BATCHN * HID];      // 64 MB  [d][s][b][h]
__device__ float g_h0 [MROWS * 2 * HID];              // 64 MB  [s][b][2H]
__device__ float g_xp1[2 * SEQL * BATCHN * HID];      // 64 MB
__device__ float g_h1 [MROWS * 2 * HID];              // 64 MB
__device__ float g_hsc[2][2][BATCHN][HID];            // 512 KB [buf][dir][b][h]

// =====================================================================
// 256x256 transpose (for building emfc_w^T)
// =====================================================================
__global__ void transpose_k(const float* __restrict__ in, float* __restrict__ out)
{
    __shared__ float tile[32][33];
    const int bx = blockIdx.x * 32, by = blockIdx.y * 32;
    int x = bx + threadIdx.x;
    #pragma unroll
    for (int i = 0; i < 32; i += 8)
        tile[threadIdx.y + i][threadIdx.x] = in[(by + threadIdx.y + i) * EMBD + x];
    __syncthreads();
    x = by + threadIdx.x;
    #pragma unroll
    for (int i = 0; i < 32; i += 8)
        out[(bx + threadIdx.y + i) * EMBD + x] = tile[threadIdx.x][threadIdx.y + i];
}

// =====================================================================
// fused bias: bf[n] = w_ih0[n,:] . emfc_b + b_ih0[n] + b_hh0[n]
// =====================================================================
__global__ void biasfuse_k(const float* __restrict__ w_ih0,
                           const float* __restrict__ emfc_b,
                           const float* __restrict__ b_ih0,
                           const float* __restrict__ b_hh0,
                           float* __restrict__ bout)
{
    const int n = blockIdx.x * 256 + threadIdx.x;
    const float* wr = w_ih0 + (size_t)n * EMBD;
    float s = 0.f;
    #pragma unroll 8
    for (int j = 0; j < EMBD; j += 4) {
        float4 w = *reinterpret_cast<const float4*>(wr + j);
        float4 b = *reinterpret_cast<const float4*>(emfc_b + j);
        s += w.x * b.x + w.y * b.y + w.z * b.z + w.w * b.w;
    }
    bout[n] = s + b_ih0[n] + b_hh0[n];
}

// =====================================================================
// fp32 SIMT GEMM, f32x2 FMA (unchanged — passing since round 5)
// =====================================================================
template<int GATHER, int SCATTER, int NBIAS, int BN>
__global__ void __launch_bounds__(256, 2)
gemm_k(const float* __restrict__ A, const float* __restrict__ Bw,
       const float* __restrict__ bias1, const float* __restrict__ bias2,
       float* __restrict__ C,
       const int* __restrict__ gidx, const float* __restrict__ gtab,
       int N, int K, int nOff, int Nfull)
{
    constexpr int BM = 128, BK = 16;
    constexpr int COLS = BN / 16;
    constexpr int BF4  = BN / 64;
    __shared__ float As[2][BK][BM];
    __shared__ float Bs[2][BK][BN];

    const int tid   = threadIdx.x;
    const int mBase = blockIdx.y * BM;
    const int nBase = blockIdx.x * BN;
    const int tx = tid & 15;
    const int ty = tid >> 4;

    const int ar0 = tid >> 2;
    const int ak4 = (tid & 3) * 4;
    const int br  = (BN == 128) ? (tid >> 1) : (tid >> 2);
    const int bko = (BN == 128) ? ((tid & 1) * 8) : ((tid & 3) * 4);

    const int row0 = mBase + ar0;
    const int row1 = row0 + 64;
    const float* arp0;
    const float* arp1;
    if (GATHER) {
        arp0 = gtab + (size_t)gidx[row0] * K;
        arp1 = gtab + (size_t)gidx[row1] * K;
    } else {
        arp0 = A + (size_t)row0 * K;
        arp1 = A + (size_t)row1 * K;
    }
    const int brow = nBase + br;
    const float* brp = (brow < N) ? (Bw + (size_t)brow * K) : nullptr;

    const int KT = K / BK;

    float4 a0r, a1r, b0r[BF4];

    a0r = *reinterpret_cast<const float4*>(arp0 + ak4);
    a1r = *reinterpret_cast<const float4*>(arp1 + ak4);
    #pragma unroll
    for (int f = 0; f < BF4; f++)
        b0r[f] = brp ? *reinterpret_cast<const float4*>(brp + bko + 4 * f)
                     : make_float4(0.f, 0.f, 0.f, 0.f);
    {
        As[0][ak4+0][ar0]    = a0r.x; As[0][ak4+1][ar0]    = a0r.y;
        As[0][ak4+2][ar0]    = a0r.z; As[0][ak4+3][ar0]    = a0r.w;
        As[0][ak4+0][ar0+64] = a1r.x; As[0][ak4+1][ar0+64] = a1r.y;
        As[0][ak4+2][ar0+64] = a1r.z; As[0][ak4+3][ar0+64] = a1r.w;
        #pragma unroll
        for (int f = 0; f < BF4; f++) {
            Bs[0][bko+4*f+0][br] = b0r[f].x; Bs[0][bko+4*f+1][br] = b0r[f].y;
            Bs[0][bko+4*f+2][br] = b0r[f].z; Bs[0][bko+4*f+3][br] = b0r[f].w;
        }
    }
    __syncthreads();

    u64 acc2[4][COLS];
    #pragma unroll
    for (int i = 0; i < 4; i++)
        #pragma unroll
        for (int j = 0; j < COLS; j++) acc2[i][j] = 0ull;

    #pragma unroll 1
    for (int kt = 0; kt < KT; kt++) {
        const int buf = kt & 1;
        if (kt + 1 < KT) {
            const int ka = (kt + 1) * BK;
            a0r = *reinterpret_cast<const float4*>(arp0 + ka + ak4);
            a1r = *reinterpret_cast<const float4*>(arp1 + ka + ak4);
            #pragma unroll
            for (int f = 0; f < BF4; f++)
                b0r[f] = brp ? *reinterpret_cast<const float4*>(brp + ka + bko + 4 * f)
                             : make_float4(0.f, 0.f, 0.f, 0.f);
        }
        #pragma unroll
        for (int k = 0; k < BK; k++) {
            ulonglong2 aA = *reinterpret_cast<const ulonglong2*>(&As[buf][k][ty * 8]);
            ulonglong2 aB = *reinterpret_cast<const ulonglong2*>(&As[buf][k][ty * 8 + 4]);
            u64 a2[4] = {aA.x, aA.y, aB.x, aB.y};
            u64 b2[COLS];
            #pragma unroll
            for (int f = 0; f < BF4; f++) {
                float4 bf = *reinterpret_cast<const float4*>(&Bs[buf][k][tx * COLS + 4 * f]);
                b2[4*f+0] = pack2(bf.x, bf.x); b2[4*f+1] = pack2(bf.y, bf.y);
                b2[4*f+2] = pack2(bf.z, bf.z); b2[4*f+3] = pack2(bf.w, bf.w);
            }
            #pragma unroll
            for (int i = 0; i < 4; i++)
                #pragma unroll
                for (int j = 0; j < COLS; j++)
                    acc2[i][j] = ffma2(a2[i], b2[j], acc2[i][j]);
        }
        if (kt + 1 < KT) {
            const int nb = (kt + 1) & 1;
            As[nb][ak4+0][ar0]    = a0r.x; As[nb][ak4+1][ar0]    = a0r.y;
            As[nb][ak4+2][ar0]    = a0r.z; As[nb][ak4+3][ar0]    = a0r.w;
            As[nb][ak4+0][ar0+64] = a1r.x; As[nb][ak4+1][ar0+64] = a1r.y;
            As[nb][ak4+2][ar0+64] = a1r.z; As[nb][ak4+3][ar0+64] = a1r.w;
            #pragma unroll
            for (int f = 0; f < BF4; f++) {
                Bs[nb][bko+4*f+0][br] = b0r[f].x; Bs[nb][bko+4*f+1][br] = b0r[f].y;
                Bs[nb][bko+4*f+2][br] = b0r[f].z; Bs[nb][bko+4*f+3][br] = b0r[f].w;
            }
            __syncthreads();
        }
    }

    #pragma unroll
    for (int i2 = 0; i2 < 4; i2++) {
        #pragma unroll
        for (int j = 0; j < COLS; j++) {
            const int n = tx * COLS + j;
            if (nBase + n >= N) continue;
            const int nglob = nBase + n + nOff;
            float2 v2 = unpk2(acc2[i2][j]);
            float bsum = 0.f;
            if (NBIAS >= 1) bsum += bias1[nglob];
            if (NBIAS >= 2) bsum += bias2[nglob];
            #pragma unroll
            for (int half = 0; half < 2; half++) {
                const int m = mBase + ty * 8 + i2 * 2 + half;
                float v = (half ? v2.y : v2.x) + bsum;
                if (SCATTER) {
                    const int s = m >> 6, b = m & 63, d = nglob >> 9, h = nglob & 511;
                    C[(size_t)d * (SEQL * BATCHN * HID) +
                      (size_t)s * (BATCHN * HID) + b * HID + h] = v;
                } else {
                    C[(size_t)m * Nfull + nglob] = v;
                }
            }
        }
    }
}

// =====================================================================
// Recurrence (EXACT round-5 form — best measured: 1431us/launch).
// 16 clusters of 8 CTAs. cluster = (dir d, batch-octet g); CTA rank r
// = 64-output slice. Warp w = k-chunk; 2 orows/thread; W in registers;
// h via L2 stcg/ldcg; cluster barrier per step; hout + xp prefetch in
// the arrive->wait window.
// =====================================================================
__global__ void __cluster_dims__(8, 1, 1) __launch_bounds__(256, 1)
rnn_k(const float* __restrict__ xp,      // [2][SEQL][BATCHN][HID]
      const float* __restrict__ whh,     // [2][HID][HID]
      float* __restrict__ hout)          // [SEQL][BATCHN][2*HID]
{
    const int r   = blockIdx.x & 7;
    const int cid = blockIdx.x >> 3;
    const int d   = cid & 1;
    const int g   = cid >> 1;
    const int t   = threadIdx.x;
    const int w   = t >> 5;              // warp index = k-chunk 0..7
    const int oo  = t & 31;
    const int o0  = r * 64 + oo;
    const int o1  = o0 + 32;
    const int ck  = w * 64;

    // --- W slices into registers as (even-k, odd-k) pairs ---
    u64 Wp0[32], Wp1[32];
    {
        const float* w0 = whh + (size_t)(d * HID + o0) * HID + ck;
        const float* w1 = whh + (size_t)(d * HID + o1) * HID + ck;
        #pragma unroll
        for (int i = 0; i < 16; i++) {
            ulonglong2 v0 = *reinterpret_cast<const ulonglong2*>(w0 + 4 * i);
            Wp0[2 * i] = v0.x; Wp0[2 * i + 1] = v0.y;
            ulonglong2 v1 = *reinterpret_cast<const ulonglong2*>(w1 + 4 * i);
            Wp1[2 * i] = v1.x; Wp1[2 * i + 1] = v1.y;
        }
    }

    // --- zero scratch buf 0 for our (d, batch-octet) slice ---
    float* sc0 = &g_hsc[0][d][g * 8][0];
    for (int i = t * 4; i < 4096; i += 1024)
        *reinterpret_cast<float4*>(sc0 + i) = make_float4(0.f, 0.f, 0.f, 0.f);

    asm volatile("barrier.cluster.arrive.aligned;" ::: "memory");
    asm volatile("barrier.cluster.wait.aligned;"   ::: "memory");

    __shared__ float h_sm[8][HID];       // 16 KB
    __shared__ float part[8][64][12];    // 24 KB

    // reduce-phase mapping: thread handles outputs (ol, b0) and (ol, b0+1)
    const int ol  = t >> 2;              // 0..63
    const int b0  = (t & 3) * 2;         // 0,2,4,6
    const int orF = r * 64 + ol;
    const int gb0 = g * 8 + b0;

    float xv0, xv1;
    {
        const int s0 = d ? (SEQL - 1) : 0;
        const float* xpb = xp + ((size_t)(d * SEQL + s0) * BATCHN) * HID;
        xv0 = xpb[(size_t)gb0 * HID + orF];
        xv1 = xpb[(size_t)(gb0 + 1) * HID + orF];
    }

    #pragma unroll 1
    for (int step = 0; step < SEQL; step++) {
        const int s = d ? (SEQL - 1 - step) : step;

        // warp-local h staging: warp w loads h[0..7][ck..ck+63]
        {
            const float* base = &g_hsc[step & 1][d][g * 8][0];
            #pragma unroll
            for (int j = 0; j < 4; j++) {
                const int flat = j * 32 + oo;           // 0..127
                const int b  = flat >> 4;
                const int kk = (flat & 15) * 4;
                float4 v = __ldcg(reinterpret_cast<const float4*>(
                                  base + (size_t)b * HID + ck + kk));
                *reinterpret_cast<float4*>(&h_sm[b][ck + kk]) = v;
            }
        }
        __syncwarp();

        u64 a0[8], a1[8];
        #pragma unroll
        for (int b = 0; b < 8; b++) { a0[b] = 0ull; a1[b] = 0ull; }
        #pragma unroll
        for (int i = 0; i < 16; i++) {
            #pragma unroll
            for (int b = 0; b < 8; b++) {
                ulonglong2 hv = *reinterpret_cast<const ulonglong2*>(&h_sm[b][ck + 4 * i]);
                a0[b] = ffma2(Wp0[2 * i],     hv.x, a0[b]);
                a0[b] = ffma2(Wp0[2 * i + 1], hv.y, a0[b]);
                a1[b] = ffma2(Wp1[2 * i],     hv.x, a1[b]);
                a1[b] = ffma2(Wp1[2 * i + 1], hv.y, a1[b]);
            }
        }
        // fold pair-lanes, store partials (4x STS.128)
        {
            float p[8], q[8];
            #pragma unroll
            for (int b = 0; b < 8; b++) {
                float2 f0 = unpk2(a0[b]); p[b] = f0.x + f0.y;
                float2 f1 = unpk2(a1[b]); q[b] = f1.x + f1.y;
            }
            *reinterpret_cast<float4*>(&part[w][oo][0])      = make_float4(p[0], p[1], p[2], p[3]);
            *reinterpret_cast<float4*>(&part[w][oo][4])      = make_float4(p[4], p[5], p[6], p[7]);
            *reinterpret_cast<float4*>(&part[w][oo + 32][0]) = make_float4(q[0], q[1], q[2], q[3]);
            *reinterpret_cast<float4*>(&part[w][oo + 32][4]) = make_float4(q[4], q[5], q[6], q[7]);
        }
        __syncthreads();

        // reduce 8 k-chunks; finalize 2 outputs per thread
        float v0 = xv0, v1 = xv1;
        #pragma unroll
        for (int c = 0; c < 8; c++) {
            float2 pv = *reinterpret_cast<const float2*>(&part[c][ol][b0]);
            v0 += pv.x; v1 += pv.y;
        }
        v0 = fmaxf(v0, 0.f);
        v1 = fmaxf(v1, 0.f);
        float* scn = &g_hsc[(step + 1) & 1][d][0][0];
        __stcg(&scn[(size_t)gb0 * HID + orF], v0);
        __stcg(&scn[(size_t)(gb0 + 1) * HID + orF], v1);

        asm volatile("barrier.cluster.arrive.aligned;" ::: "memory");

        // hidden in the barrier window: hout stores + next-step xp prefetch
        {
            float* ho = hout + ((size_t)s * BATCHN + gb0) * (2 * HID) + d * HID + orF;
            ho[0]       = v0;
            ho[2 * HID] = v1;
        }
        if (step + 1 < SEQL) {
            const int sn = d ? (SEQL - 2 - step) : (step + 1);
            const float* xpb = xp + ((size_t)(d * SEQL + sn) * BATCHN) * HID;
            xv0 = xpb[(size_t)gb0 * HID + orF];
            xv1 = xpb[(size_t)(gb0 + 1) * HID + orF];
        }

        asm volatile("barrier.cluster.wait.aligned;" ::: "memory");
    }
}

// =====================================================================
extern "C" void kernel_launch(void* const* d_in, const int* in_sizes, int n_in,
                              void* d_out, int out_size)
{
    const int*   text   = (const int*)  d_in[0];
    const float* emb    = (const float*)d_in[1];
    const float* emfc_w = (const float*)d_in[2];
    const float* emfc_b = (const float*)d_in[3];
    const float* w_ih0  = (const float*)d_in[4];
    const float* w_hh0  = (const float*)d_in[5];
    const float* b_ih0  = (const float*)d_in[6];
    const float* b_hh0  = (const float*)d_in[7];
    const float* w_ih1  = (const float*)d_in[8];
    const float* w_hh1  = (const float*)d_in[9];
    const float* b_ih1  = (const float*)d_in[10];
    const float* b_hh1  = (const float*)d_in[11];
    const float* fc_w   = (const float*)d_in[12];
    const float* fc_b   = (const float*)d_in[13];
    float* out = (float*)d_out;

    float *p_eT, *p_M, *p_bf, *p_xp0, *p_h0, *p_xp1, *p_h1;
    cudaGetSymbolAddress((void**)&p_eT,  g_emfcT);
    cudaGetSymbolAddress((void**)&p_M,   g_M);
    cudaGetSymbolAddress((void**)&p_bf,  g_bf);
    cudaGetSymbolAddress((void**)&p_xp0, g_xp0);
    cudaGetSymbolAddress((void**)&p_h0,  g_h0);
    cudaGetSymbolAddress((void**)&p_xp1, g_xp1);
    cudaGetSymbolAddress((void**)&p_h1,  g_h1);

    dim3 blk(256);

    // 0) emfcT = emfc_w^T                                              [256,256]
    transpose_k<<<dim3(8, 8), dim3(32, 8)>>>(emfc_w, p_eT);

    // 1) M = w_ih0 @ emfc_w   (via A=w_ih0, Bw=emfcT)                  [1024,256]
    gemm_k<0,0,0,128><<<dim3(2, 8), blk>>>(
        w_ih0, p_eT, nullptr, nullptr, p_M, nullptr, nullptr, EMBD, EMBD, 0, EMBD);

    // 2) bf = w_ih0 @ emfc_b + b_ih0 + b_hh0                           [1024]
    biasfuse_k<<<4, 256>>>(w_ih0, emfc_b, b_ih0, b_hh0, p_bf);

    // 3-4) xp0 = gather(emb, text) @ M^T + bf  (fused; post_emb eliminated)
    gemm_k<1,1,1,128><<<dim3(512/128, MROWS/128), blk>>>(
        nullptr, p_M, p_bf, nullptr, p_xp0, text, emb, 512, EMBD, 0, 0);
    gemm_k<1,1,1,128><<<dim3(512/128, MROWS/128), blk>>>(
        nullptr, p_M + (size_t)512 * EMBD, p_bf, nullptr, p_xp0,
        text, emb, 512, EMBD, 512, 0);

    // 5) layer-0 bidirectional recurrence -> h0 [s][b][1024]   (ncu index 5)
    rnn_k<<<128, blk>>>(p_xp0, w_hh0, p_h0);

    // 6) xp1 = h0 @ w_ih1^T + (b_ih1+b_hh1)                            N=1024,K=1024
    gemm_k<0,1,2,128><<<dim3(1024/128, MROWS/128), blk>>>(
        p_h0, w_ih1, b_ih1, b_hh1, p_xp1, nullptr, nullptr, 1024, 1024, 0, 0);

    // 7) layer-1 recurrence -> h1
    rnn_k<<<128, blk>>>(p_xp1, w_hh1, p_h1);

    // 8) out = h1 @ fc_w^T + fc_b                                      N=18,K=1024
    gemm_k<0,0,1,64><<<dim3(1, MROWS/128), blk>>>(
        p_h1, fc_w, fc_b, nullptr, out, nullptr, nullptr, OUTD, 1024, 0, OUTD);
}

// round 13
// speedup vs baseline: 1.5336x; 1.5336x over previous
#include <cuda_runtime.h>
#include <cuda_bf16.h>
#include <cstdint>

#define SEQL  256
#define BATCHN 64
#define EMBD  256
#define HID   512
#define OUTD  18
#define MROWS (SEQL*BATCHN)   // 16384

typedef unsigned long long u64;

// ---------------- packed f32x2 helpers ----------------
__device__ __forceinline__ u64 ffma2(u64 a, u64 b, u64 c) {
    u64 d; asm("fma.rn.f32x2 %0, %1, %2, %3;" : "=l"(d) : "l"(a), "l"(b), "l"(c));
    return d;
}
__device__ __forceinline__ u64 pack2(float lo, float hi) {
    u64 r; asm("mov.b64 %0, {%1, %2};" : "=l"(r) : "f"(lo), "f"(hi));
    return r;
}
__device__ __forceinline__ float2 unpk2(u64 v) {
    float lo, hi; asm("mov.b64 {%0, %1}, %2;" : "=f"(lo), "=f"(hi) : "l"(v));
    return make_float2(lo, hi);
}

// ---------------- mbarrier helpers (protocol validated rounds 7 & 11) ----------------
__device__ __forceinline__ void mbar_init(uint32_t addr, uint32_t count) {
    asm volatile("mbarrier.init.shared.b64 [%0], %1;" :: "r"(addr), "r"(count) : "memory");
}
__device__ __forceinline__ void mbar_arrive_remote(uint32_t local_addr, uint32_t rank) {
    asm volatile(
        "{\n\t.reg .b32 ra;\n\t"
        "mapa.shared::cluster.u32 ra, %0, %1;\n\t"
        "mbarrier.arrive.release.cluster.shared::cluster.b64 _, [ra];\n\t}"
        :: "r"(local_addr), "r"(rank) : "memory");
}
__device__ __forceinline__ void mbar_wait_acq_cluster(uint32_t addr, uint32_t parity) {
    uint32_t done;
    asm volatile(
        "{\n\t.reg .pred p;\n\t"
        "mbarrier.try_wait.parity.acquire.cluster.shared::cta.b64 p, [%1], %2;\n\t"
        "selp.b32 %0, 1, 0, p;\n\t}"
        : "=r"(done) : "r"(addr), "r"(parity) : "memory");
    if (!done) {
        asm volatile(
            "{\n\t.reg .pred P1;\n\t"
            "WL_%=:\n\t"
            "mbarrier.try_wait.parity.acquire.cluster.shared::cta.b64 P1, [%0], %1, 0x989680;\n\t"
            "@P1 bra.uni WD_%=;\n\t"
            "bra.uni WL_%=;\n\t"
            "WD_%=:\n\t}"
            :: "r"(addr), "r"(parity) : "memory");
    }
}

// ---------------- scratch (static device arrays; no allocation) ----------------
__device__ float g_post_emb[MROWS * EMBD];            // 16 MB
__device__ float g_xp0[2 * SEQL * BATCHN * HID];      // 64 MB  [d][s][b][h]
__device__ float g_h0 [MROWS * 2 * HID];              // 64 MB  [s][b][2H]
__device__ float g_xp1[2 * SEQL * BATCHN * HID];      // 64 MB
__device__ float g_h1 [MROWS * 2 * HID];              // 64 MB
__device__ float g_hsc[4][2][BATCHN][HID];            // 1 MB ring [slot][dir][b][h]

// =====================================================================
// fp32 SIMT GEMM, f32x2 FMA (unchanged — round-5 form)
// =====================================================================
template<int GATHER, int SCATTER, int NBIAS, int BN>
__global__ void __launch_bounds__(256, 2)
gemm_k(const float* __restrict__ A, const float* __restrict__ Bw,
       const float* __restrict__ bias1, const float* __restrict__ bias2,
       float* __restrict__ C,
       const int* __restrict__ gidx, const float* __restrict__ gtab,
       int N, int K, int nOff, int Nfull)
{
    constexpr int BM = 128, BK = 16;
    constexpr int COLS = BN / 16;
    constexpr int BF4  = BN / 64;
    __shared__ float As[2][BK][BM];
    __shared__ float Bs[2][BK][BN];

    const int tid   = threadIdx.x;
    const int mBase = blockIdx.y * BM;
    const int nBase = blockIdx.x * BN;
    const int tx = tid & 15;
    const int ty = tid >> 4;

    const int ar0 = tid >> 2;
    const int ak4 = (tid & 3) * 4;
    const int br  = (BN == 128) ? (tid >> 1) : (tid >> 2);
    const int bko = (BN == 128) ? ((tid & 1) * 8) : ((tid & 3) * 4);

    const int row0 = mBase + ar0;
    const int row1 = row0 + 64;
    const float* arp0;
    const float* arp1;
    if (GATHER) {
        arp0 = gtab + (size_t)gidx[row0] * K;
        arp1 = gtab + (size_t)gidx[row1] * K;
    } else {
        arp0 = A + (size_t)row0 * K;
        arp1 = A + (size_t)row1 * K;
    }
    const int brow = nBase + br;
    const float* brp = (brow < N) ? (Bw + (size_t)brow * K) : nullptr;

    const int KT = K / BK;

    float4 a0r, a1r, b0r[BF4];

    a0r = *reinterpret_cast<const float4*>(arp0 + ak4);
    a1r = *reinterpret_cast<const float4*>(arp1 + ak4);
    #pragma unroll
    for (int f = 0; f < BF4; f++)
        b0r[f] = brp ? *reinterpret_cast<const float4*>(brp + bko + 4 * f)
                     : make_float4(0.f, 0.f, 0.f, 0.f);
    {
        As[0][ak4+0][ar0]    = a0r.x; As[0][ak4+1][ar0]    = a0r.y;
        As[0][ak4+2][ar0]    = a0r.z; As[0][ak4+3][ar0]    = a0r.w;
        As[0][ak4+0][ar0+64] = a1r.x; As[0][ak4+1][ar0+64] = a1r.y;
        As[0][ak4+2][ar0+64] = a1r.z; As[0][ak4+3][ar0+64] = a1r.w;
        #pragma unroll
        for (int f = 0; f < BF4; f++) {
            Bs[0][bko+4*f+0][br] = b0r[f].x; Bs[0][bko+4*f+1][br] = b0r[f].y;
            Bs[0][bko+4*f+2][br] = b0r[f].z; Bs[0][bko+4*f+3][br] = b0r[f].w;
        }
    }
    __syncthreads();

    u64 acc2[4][COLS];
    #pragma unroll
    for (int i = 0; i < 4; i++)
        #pragma unroll
        for (int j = 0; j < COLS; j++) acc2[i][j] = 0ull;

    #pragma unroll 1
    for (int kt = 0; kt < KT; kt++) {
        const int buf = kt & 1;
        if (kt + 1 < KT) {
            const int ka = (kt + 1) * BK;
            a0r = *reinterpret_cast<const float4*>(arp0 + ka + ak4);
            a1r = *reinterpret_cast<const float4*>(arp1 + ka + ak4);
            #pragma unroll
            for (int f = 0; f < BF4; f++)
                b0r[f] = brp ? *reinterpret_cast<const float4*>(brp + ka + bko + 4 * f)
                             : make_float4(0.f, 0.f, 0.f, 0.f);
        }
        #pragma unroll
        for (int k = 0; k < BK; k++) {
            ulonglong2 aA = *reinterpret_cast<const ulonglong2*>(&As[buf][k][ty * 8]);
            ulonglong2 aB = *reinterpret_cast<const ulonglong2*>(&As[buf][k][ty * 8 + 4]);
            u64 a2[4] = {aA.x, aA.y, aB.x, aB.y};
            u64 b2[COLS];
            #pragma unroll
            for (int f = 0; f < BF4; f++) {
                float4 bf = *reinterpret_cast<const float4*>(&Bs[buf][k][tx * COLS + 4 * f]);
                b2[4*f+0] = pack2(bf.x, bf.x); b2[4*f+1] = pack2(bf.y, bf.y);
                b2[4*f+2] = pack2(bf.z, bf.z); b2[4*f+3] = pack2(bf.w, bf.w);
            }
            #pragma unroll
            for (int i = 0; i < 4; i++)
                #pragma unroll
                for (int j = 0; j < COLS; j++)
                    acc2[i][j] = ffma2(a2[i], b2[j], acc2[i][j]);
        }
        if (kt + 1 < KT) {
            const int nb = (kt + 1) & 1;
            As[nb][ak4+0][ar0]    = a0r.x; As[nb][ak4+1][ar0]    = a0r.y;
            As[nb][ak4+2][ar0]    = a0r.z; As[nb][ak4+3][ar0]    = a0r.w;
            As[nb][ak4+0][ar0+64] = a1r.x; As[nb][ak4+1][ar0+64] = a1r.y;
            As[nb][ak4+2][ar0+64] = a1r.z; As[nb][ak4+3][ar0+64] = a1r.w;
            #pragma unroll
            for (int f = 0; f < BF4; f++) {
                Bs[nb][bko+4*f+0][br] = b0r[f].x; Bs[nb][bko+4*f+1][br] = b0r[f].y;
                Bs[nb][bko+4*f+2][br] = b0r[f].z; Bs[nb][bko+4*f+3][br] = b0r[f].w;
            }
            __syncthreads();
        }
    }

    #pragma unroll
    for (int i2 = 0; i2 < 4; i2++) {
        #pragma unroll
        for (int j = 0; j < COLS; j++) {
            const int n = tx * COLS + j;
            if (nBase + n >= N) continue;
            const int nglob = nBase + n + nOff;
            float2 v2 = unpk2(acc2[i2][j]);
            float bsum = 0.f;
            if (NBIAS >= 1) bsum += bias1[nglob];
            if (NBIAS >= 2) bsum += bias2[nglob];
            #pragma unroll
            for (int half = 0; half < 2; half++) {
                const int m = mBase + ty * 8 + i2 * 2 + half;
                float v = (half ? v2.y : v2.x) + bsum;
                if (SCATTER) {
                    const int s = m >> 6, b = m & 63, d = nglob >> 9, h = nglob & 511;
                    C[(size_t)d * (SEQL * BATCHN * HID) +
                      (size_t)s * (BATCHN * HID) + b * HID + h] = v;
                } else {
                    C[(size_t)m * Nfull + nglob] = v;
                }
            }
        }
    }
}

// =====================================================================
// Recurrence v6 — QUARTET DUAL-STREAM at full parallelism.
// 16 clusters x 8 CTAs (128 CTAs, as round 5). cluster = (dir d, octet
// g); CTA rank r = 64 outputs. Each CTA interleaves stream A = batches
// g*8..+3 and B = g*8+4..+7, sharing the register W slice. Protocol =
// round-11-validated 2-deep mbar ring per stream (wait slot step&1,
// parity (step>>1)&1, publish slot (step+1)&1) + 4-slot L2 h ring.
// Each stream's publish->visibility latency hides under the sibling
// quartet's compute. Separate smem buffers per phase (no WAR barriers).
// =====================================================================
__global__ void __cluster_dims__(8, 1, 1) __launch_bounds__(256, 1)
rnn_k(const float* __restrict__ xp,      // [2][SEQL][BATCHN][HID]
      const float* __restrict__ whh,     // [2][HID][HID]
      float* __restrict__ hout)          // [SEQL][BATCHN][2*HID]
{
    const int r   = blockIdx.x & 7;      // cluster_ctarank
    const int cid = blockIdx.x >> 3;
    const int d   = cid & 1;
    const int g   = cid >> 1;
    const int t   = threadIdx.x;
    const int w   = t >> 5;              // warp = k-chunk 0..7
    const int oo  = t & 31;
    const int o0  = r * 64 + oo;
    const int o1  = o0 + 32;
    const int ck  = w * 64;

    __shared__ float hA[4][HID];         // 8 KB
    __shared__ float hB[4][HID];         // 8 KB
    __shared__ float pA[8][4][64];       // 4 KB   [chunk][batch][orow]
    __shared__ float pB[8][4][64];       // 4 KB
    __shared__ __align__(8) u64 mbarA[16];   // [slot][producer]
    __shared__ __align__(8) u64 mbarB[16];

    uint32_t mbA, mbB;
    asm("{ .reg .u64 tt; cvta.to.shared.u64 tt, %1; cvt.u32.u64 %0, tt; }"
        : "=r"(mbA) : "l"((void*)mbarA));
    asm("{ .reg .u64 tt; cvta.to.shared.u64 tt, %1; cvt.u32.u64 %0, tt; }"
        : "=r"(mbB) : "l"((void*)mbarB));

    // --- W slice (2 output rows x 64 k): (even,odd) packed pairs ---
    u64 Wp0[32], Wp1[32];
    {
        const float* w0 = whh + (size_t)(d * HID + o0) * HID + ck;
        const float* w1 = whh + (size_t)(d * HID + o1) * HID + ck;
        #pragma unroll
        for (int i = 0; i < 16; i++) {
            ulonglong2 v0 = *reinterpret_cast<const ulonglong2*>(w0 + 4 * i);
            Wp0[2 * i] = v0.x; Wp0[2 * i + 1] = v0.y;
            ulonglong2 v1 = *reinterpret_cast<const ulonglong2*>(w1 + 4 * i);
            Wp1[2 * i] = v1.x; Wp1[2 * i + 1] = v1.y;
        }
    }

    if (t < 16) { mbar_init(mbA + t * 8, 1); mbar_init(mbB + t * 8, 1); }

    // zero ring slot 0 for our octet (both quartets)
    {
        float* sc0 = &g_hsc[0][d][g * 8][0];
        for (int i = t * 4; i < 4096; i += 1024)
            __stcg(reinterpret_cast<float4*>(sc0 + i), make_float4(0.f, 0.f, 0.f, 0.f));
    }
    __syncthreads();
    asm volatile("barrier.cluster.arrive.aligned;" ::: "memory");
    asm volatile("barrier.cluster.wait.aligned;"   ::: "memory");

    // prime slot 0 of both streams (consumed by step-0 waits, parity 0)
    if (t < 8) { mbar_arrive_remote(mbA + r * 8, (uint32_t)t);
                 mbar_arrive_remote(mbB + r * 8, (uint32_t)t); }

    // reduce mapping: thread -> one (output, quartet-batch)
    const int ol  = t & 63;              // output 0..63
    const int bq  = t >> 6;              // quartet batch 0..3
    const int orF = r * 64 + ol;
    const int bAg = g * 8 + bq;          // stream A global batch
    const int bBg = g * 8 + 4 + bq;      // stream B global batch

    float xvA, xvB;
    {
        const int s0 = d ? (SEQL - 1) : 0;
        const float* xpb = xp + ((size_t)(d * SEQL + s0) * BATCHN) * HID;
        xvA = xpb[(size_t)bAg * HID + orF];
        xvB = xpb[(size_t)bBg * HID + orF];
    }

    #pragma unroll 1
    for (int step = 0; step < SEQL; step++) {
        const int s  = d ? (SEQL - 1 - step) : step;
        const int rd = step & 3;
        const int wr = (step + 1) & 3;
        const uint32_t wslot = (uint32_t)(step & 1);
        const uint32_t par   = (uint32_t)((step >> 1) & 1);
        const uint32_t pslot = (uint32_t)((step + 1) & 1);

        // ======== phase A (batches g*8 .. g*8+3) ========
        mbar_wait_acq_cluster(mbA + (wslot * 8 + w) * 8, par);
        {
            const float* base = &g_hsc[rd][d][g * 8][0];
            #pragma unroll
            for (int jj = 0; jj < 2; jj++) {
                const int flat = jj * 32 + oo;          // 0..63
                const int b  = flat >> 4;               // 0..3
                const int kk = (flat & 15) * 4;
                float4 v = __ldcg(reinterpret_cast<const float4*>(
                                  base + (size_t)b * HID + ck + kk));
                *reinterpret_cast<float4*>(&hA[b][ck + kk]) = v;
            }
        }
        __syncwarp();
        {
            u64 a0[4] = {0ull,0ull,0ull,0ull}, a1[4] = {0ull,0ull,0ull,0ull};
            #pragma unroll
            for (int i = 0; i < 16; i++) {
                #pragma unroll
                for (int b = 0; b < 4; b++) {
                    ulonglong2 hv = *reinterpret_cast<const ulonglong2*>(&hA[b][ck + 4 * i]);
                    a0[b] = ffma2(Wp0[2 * i],     hv.x, a0[b]);
                    a0[b] = ffma2(Wp0[2 * i + 1], hv.y, a0[b]);
                    a1[b] = ffma2(Wp1[2 * i],     hv.x, a1[b]);
                    a1[b] = ffma2(Wp1[2 * i + 1], hv.y, a1[b]);
                }
            }
            #pragma unroll
            for (int b = 0; b < 4; b++) {
                float2 f0 = unpk2(a0[b]); pA[w][b][oo]      = f0.x + f0.y;
                float2 f1 = unpk2(a1[b]); pA[w][b][oo + 32] = f1.x + f1.y;
            }
        }
        __syncthreads();
        {
            float v = xvA;
            #pragma unroll
            for (int c = 0; c < 8; c++) v += pA[c][bq][ol];
            v = fmaxf(v, 0.f);
            __stcg(&g_hsc[wr][d][0][0] + (size_t)bAg * HID + orF, v);
            __syncthreads();                       // all A-stcg done before release
            if (step + 1 < SEQL && t < 8)
                mbar_arrive_remote(mbA + (pslot * 8 + r) * 8, (uint32_t)t);
            hout[((size_t)s * BATCHN + bAg) * (2 * HID) + d * HID + orF] = v;
            if (step + 1 < SEQL) {
                const int sn = d ? (SEQL - 2 - step) : (step + 1);
                xvA = xp[((size_t)(d * SEQL + sn) * BATCHN + bAg) * HID + orF];
            }
        }

        // ======== phase B (batches g*8+4 .. g*8+7) ========
        mbar_wait_acq_cluster(mbB + (wslot * 8 + w) * 8, par);
        {
            const float* base = &g_hsc[rd][d][g * 8 + 4][0];
            #pragma unroll
            for (int jj = 0; jj < 2; jj++) {
                const int flat = jj * 32 + oo;
                const int b  = flat >> 4;
                const int kk = (flat & 15) * 4;
                float4 v = __ldcg(reinterpret_cast<const float4*>(
                                  base + (size_t)b * HID + ck + kk));
                *reinterpret_cast<float4*>(&hB[b][ck + kk]) = v;
            }
        }
        __syncwarp();
        {
            u64 a0[4] = {0ull,0ull,0ull,0ull}, a1[4] = {0ull,0ull,0ull,0ull};
            #pragma unroll
            for (int i = 0; i < 16; i++) {
                #pragma unroll
                for (int b = 0; b < 4; b++) {
                    ulonglong2 hv = *reinterpret_cast<const ulonglong2*>(&hB[b][ck + 4 * i]);
                    a0[b] = ffma2(Wp0[2 * i],     hv.x, a0[b]);
                    a0[b] = ffma2(Wp0[2 * i + 1], hv.y, a0[b]);
                    a1[b] = ffma2(Wp1[2 * i],     hv.x, a1[b]);
                    a1[b] = ffma2(Wp1[2 * i + 1], hv.y, a1[b]);
                }
            }
            #pragma unroll
            for (int b = 0; b < 4; b++) {
                float2 f0 = unpk2(a0[b]); pB[w][b][oo]      = f0.x + f0.y;
                float2 f1 = unpk2(a1[b]); pB[w][b][oo + 32] = f1.x + f1.y;
            }
        }
        __syncthreads();
        {
            float v = xvB;
            #pragma unroll
            for (int c = 0; c < 8; c++) v += pB[c][bq][ol];
            v = fmaxf(v, 0.f);
            __stcg(&g_hsc[wr][d][0][0] + (size_t)bBg * HID + orF, v);
            __syncthreads();                       // all B-stcg done before release
            if (step + 1 < SEQL && t < 8)
                mbar_arrive_remote(mbB + (pslot * 8 + r) * 8, (uint32_t)t);
            hout[((size_t)s * BATCHN + bBg) * (2 * HID) + d * HID + orF] = v;
            if (step + 1 < SEQL) {
                const int sn = d ? (SEQL - 2 - step) : (step + 1);
                xvB = xp[((size_t)(d * SEQL + sn) * BATCHN + bBg) * HID + orF];
            }
        }
    }
}

// =====================================================================
extern "C" void kernel_launch(void* const* d_in, const int* in_sizes, int n_in,
                              void* d_out, int out_size)
{
    const int*   text   = (const int*)  d_in[0];
    const float* emb    = (const float*)d_in[1];
    const float* emfc_w = (const float*)d_in[2];
    const float* emfc_b = (const float*)d_in[3];
    const float* w_ih0  = (const float*)d_in[4];
    const float* w_hh0  = (const float*)d_in[5];
    const float* b_ih0  = (const float*)d_in[6];
    const float* b_hh0  = (const float*)d_in[7];
    const float* w_ih1  = (const float*)d_in[8];
    const float* w_hh1  = (const float*)d_in[9];
    const float* b_ih1  = (const float*)d_in[10];
    const float* b_hh1  = (const float*)d_in[11];
    const float* fc_w   = (const float*)d_in[12];
    const float* fc_b   = (const float*)d_in[13];
    float* out = (float*)d_out;

    float *p_pe, *p_xp0, *p_h0, *p_xp1, *p_h1;
    cudaGetSymbolAddress((void**)&p_pe,  g_post_emb);
    cudaGetSymbolAddress((void**)&p_xp0, g_xp0);
    cudaGetSymbolAddress((void**)&p_h0,  g_h0);
    cudaGetSymbolAddress((void**)&p_xp1, g_xp1);
    cudaGetSymbolAddress((void**)&p_h1,  g_h1);

    dim3 blk(256);

    // 0) post_emb = gather(emb_table, text) @ emfc_w^T + emfc_b  (gather ONCE)
    gemm_k<1,0,1,128><<<dim3(EMBD/128, MROWS/128), blk>>>(
        nullptr, emfc_w, emfc_b, nullptr, p_pe, text, emb, EMBD, EMBD, 0, EMBD);

    // 1-2) xp0 split by direction
    gemm_k<0,1,2,128><<<dim3(512/128, MROWS/128), blk>>>(
        p_pe, w_ih0, b_ih0, b_hh0, p_xp0, nullptr, nullptr, 512, EMBD, 0, 0);
    gemm_k<0,1,2,128><<<dim3(512/128, MROWS/128), blk>>>(
        p_pe, w_ih0 + (size_t)512 * EMBD, b_ih0, b_hh0, p_xp0,
        nullptr, nullptr, 512, EMBD, 512, 0);

    // 3) layer-0 recurrence -> h0 [s][b][1024]   (ncu captures index 3)
    rnn_k<<<128, blk>>>(p_xp0, w_hh0, p_h0);

    // 4) xp1 = h0 @ w_ih1^T + (b_ih1+b_hh1)
    gemm_k<0,1,2,128><<<dim3(1024/128, MROWS/128), blk>>>(
        p_h0, w_ih1, b_ih1, b_hh1, p_xp1, nullptr, nullptr, 1024, 1024, 0, 0);

    // 5) layer-1 recurrence -> h1
    rnn_k<<<128, blk>>>(p_xp1, w_hh1, p_h1);

    // 6) out = h1 @ fc_w^T + fc_b
    gemm_k<0,0,1,64><<<dim3(1, MROWS/128), blk>>>(
        p_h1, fc_w, fc_b, nullptr, out, nullptr, nullptr, OUTD, 1024, 0, OUTD);
}

// round 16
// speedup vs baseline: 1.7697x; 1.1540x over previous
#include <cuda_runtime.h>
#include <cuda_bf16.h>
#include <cstdint>

#define SEQL  256
#define BATCHN 64
#define EMBD  256
#define HID   512
#define OUTD  18
#define MROWS (SEQL*BATCHN)   // 16384

typedef unsigned long long u64;

// ---------------- packed f32x2 helpers ----------------
__device__ __forceinline__ u64 ffma2(u64 a, u64 b, u64 c) {
    u64 d; asm("fma.rn.f32x2 %0, %1, %2, %3;" : "=l"(d) : "l"(a), "l"(b), "l"(c));
    return d;
}
__device__ __forceinline__ u64 pack2(float lo, float hi) {
    u64 r; asm("mov.b64 %0, {%1, %2};" : "=l"(r) : "f"(lo), "f"(hi));
    return r;
}
__device__ __forceinline__ float2 unpk2(u64 v) {
    float lo, hi; asm("mov.b64 {%0, %1}, %2;" : "=f"(lo), "=f"(hi) : "l"(v));
    return make_float2(lo, hi);
}
__device__ __forceinline__ uint32_t smem_u32(const void* p) {
    uint32_t a;
    asm("{ .reg .u64 tt; cvta.to.shared.u64 tt, %1; cvt.u32.u64 %0, tt; }" : "=r"(a) : "l"(p));
    return a;
}

// ---------------- mma.sync / ldmatrix (baseline PTX, sm_80+) ----------------
#define LDMATRIX_X4(r0, r1, r2, r3, addr) \
    asm volatile("ldmatrix.sync.aligned.m8n8.x4.shared.b16 {%0,%1,%2,%3}, [%4];" \
        : "=r"(r0), "=r"(r1), "=r"(r2), "=r"(r3) : "r"(addr))

#define MMA_BF16(c, a, b0v, b1v) \
    asm volatile("mma.sync.aligned.m16n8k16.row.col.f32.bf16.bf16.f32 " \
        "{%0,%1,%2,%3}, {%4,%5,%6,%7}, {%8,%9}, {%0,%1,%2,%3};" \
        : "+f"((c)[0]), "+f"((c)[1]), "+f"((c)[2]), "+f"((c)[3]) \
        : "r"((a)[0]), "r"((a)[1]), "r"((a)[2]), "r"((a)[3]), "r"(b0v), "r"(b1v))

// ---------------- scratch (static device arrays; no allocation) ----------------
__device__ float g_post_emb[MROWS * EMBD];            // 16 MB
__device__ float g_xp0[2 * SEQL * BATCHN * HID];      // 64 MB  [d][s][b][h]
__device__ float g_h0 [MROWS * 2 * HID];              // 64 MB  [s][b][2H]
__device__ float g_xp1[2 * SEQL * BATCHN * HID];      // 64 MB
__device__ float g_h1 [MROWS * 2 * HID];              // 64 MB
__device__ float g_hsc[2][2][BATCHN][HID];            // 512 KB [buf][dir][b][h]
__device__ __nv_bfloat16 g_wh0[1024 * EMBD];          // w_ih0 hi
__device__ __nv_bfloat16 g_wl0[1024 * EMBD];          // w_ih0 lo
__device__ __nv_bfloat16 g_wh1[1024 * 1024];          // w_ih1 hi
__device__ __nv_bfloat16 g_wl1[1024 * 1024];          // w_ih1 lo

// =====================================================================
// weight split: fp32 -> bf16 hi + bf16 lo
// =====================================================================
__global__ void wconv_k(const float* __restrict__ w,
                        __nv_bfloat16* __restrict__ wh,
                        __nv_bfloat16* __restrict__ wl, int n)
{
    int i = blockIdx.x * 256 + threadIdx.x;
    if (i < n) {
        float x = w[i];
        __nv_bfloat16 h = __float2bfloat16(x);
        wh[i] = h;
        wl[i] = __float2bfloat16(x - __bfloat162float(h));
    }
}

// =====================================================================
// split-bf16 3-pass mma.sync xp GEMM:
//   xp[d][s][b][h] = A[16384,K] @ W[1024,K]^T + bias1 + bias2
// CTA tile 128x128, warp tile 32x64, BK=32, 8 warps.
// smem stride 40 bf16 (80B: 16B aligned, bank-rotating).
// Passes: Ah*Bh + Ah*Bl + Al*Bh (AlBl term ~4e-6, dropped).
// =====================================================================
#define TCS 40   // smem row stride in bf16

__global__ void __launch_bounds__(256, 1)
mma_xp_k(const float* __restrict__ A, int K,
         const __nv_bfloat16* __restrict__ Wh, const __nv_bfloat16* __restrict__ Wl,
         const float* __restrict__ bias1, const float* __restrict__ bias2,
         float* __restrict__ xp)
{
    __shared__ __nv_bfloat16 Ah[128][TCS], Al[128][TCS];
    __shared__ __nv_bfloat16 Bh[128][TCS], Bl[128][TCS];

    const int tid  = threadIdx.x;
    const int wid  = tid >> 5;
    const int lane = tid & 31;
    const int nBase = blockIdx.x * 128;
    const int mBase = blockIdx.y * 128;
    const int warpM = (wid >> 1) * 32;   // 4 warps over M
    const int warpN = (wid & 1) * 64;    // 2 warps over N

    // staging assignment: row = tid>>1 (0..127), half = tid&1 (k 0-15 / 16-31)
    const int srow  = tid >> 1;
    const int shalf = (tid & 1) * 16;
    const float* arow = A + (size_t)(mBase + srow) * K + shalf;
    const __nv_bfloat16* whrow = Wh + (size_t)(nBase + srow) * K + shalf;
    const __nv_bfloat16* wlrow = Wl + (size_t)(nBase + srow) * K + shalf;

    // ldmatrix source addresses (canonical m16n8k16 fragment layouts)
    const int aRow = lane & 15;
    const int aKo  = (lane >> 4) << 3;
    const int bRow = (lane & 7) + ((lane >> 4) << 3);
    const int bKo  = ((lane >> 3) & 1) << 3;

    float acc[2][8][4];
    #pragma unroll
    for (int mi = 0; mi < 2; mi++)
        #pragma unroll
        for (int ni = 0; ni < 8; ni++)
            #pragma unroll
            for (int c = 0; c < 4; c++) acc[mi][ni][c] = 0.f;

    const int nkc = K >> 5;
    #pragma unroll 1
    for (int kc = 0; kc < nkc; kc++) {
        __syncthreads();
        // ---- stage A (fp32 -> hi/lo bf16) ----
        {
            const float* ap = arow + kc * 32;
            float4 v0 = *reinterpret_cast<const float4*>(ap);
            float4 v1 = *reinterpret_cast<const float4*>(ap + 4);
            float4 v2 = *reinterpret_cast<const float4*>(ap + 8);
            float4 v3 = *reinterpret_cast<const float4*>(ap + 12);
            float vv[16] = {v0.x,v0.y,v0.z,v0.w, v1.x,v1.y,v1.z,v1.w,
                            v2.x,v2.y,v2.z,v2.w, v3.x,v3.y,v3.z,v3.w};
            __nv_bfloat16 hh[16], ll[16];
            #pragma unroll
            for (int i = 0; i < 16; i++) {
                hh[i] = __float2bfloat16(vv[i]);
                ll[i] = __float2bfloat16(vv[i] - __bfloat162float(hh[i]));
            }
            *reinterpret_cast<uint4*>(&Ah[srow][shalf])     = *reinterpret_cast<uint4*>(&hh[0]);
            *reinterpret_cast<uint4*>(&Ah[srow][shalf + 8]) = *reinterpret_cast<uint4*>(&hh[8]);
            *reinterpret_cast<uint4*>(&Al[srow][shalf])     = *reinterpret_cast<uint4*>(&ll[0]);
            *reinterpret_cast<uint4*>(&Al[srow][shalf + 8]) = *reinterpret_cast<uint4*>(&ll[8]);
        }
        // ---- stage B (pre-split bf16) ----
        {
            const __nv_bfloat16* bh = whrow + kc * 32;
            const __nv_bfloat16* bl = wlrow + kc * 32;
            uint4 h0 = *reinterpret_cast<const uint4*>(bh);
            uint4 h1 = *reinterpret_cast<const uint4*>(bh + 8);
            uint4 l0 = *reinterpret_cast<const uint4*>(bl);
            uint4 l1 = *reinterpret_cast<const uint4*>(bl + 8);
            *reinterpret_cast<uint4*>(&Bh[srow][shalf])     = h0;
            *reinterpret_cast<uint4*>(&Bh[srow][shalf + 8]) = h1;
            *reinterpret_cast<uint4*>(&Bl[srow][shalf])     = l0;
            *reinterpret_cast<uint4*>(&Bl[srow][shalf + 8]) = l1;
        }
        __syncthreads();

        // ---- compute: 2 k-steps of 16 ----
        #pragma unroll
        for (int ks = 0; ks < 2; ks++) {
            const int kk = ks * 16;
            uint32_t ah[2][4], al[2][4];
            #pragma unroll
            for (int mi = 0; mi < 2; mi++) {
                uint32_t adr = smem_u32(&Ah[warpM + mi * 16 + aRow][kk + aKo]);
                LDMATRIX_X4(ah[mi][0], ah[mi][1], ah[mi][2], ah[mi][3], adr);
                adr = smem_u32(&Al[warpM + mi * 16 + aRow][kk + aKo]);
                LDMATRIX_X4(al[mi][0], al[mi][1], al[mi][2], al[mi][3], adr);
            }
            uint32_t bh[4][4], bl[4][4];
            #pragma unroll
            for (int p = 0; p < 4; p++) {
                uint32_t adr = smem_u32(&Bh[warpN + p * 16 + bRow][kk + bKo]);
                LDMATRIX_X4(bh[p][0], bh[p][1], bh[p][2], bh[p][3], adr);
                adr = smem_u32(&Bl[warpN + p * 16 + bRow][kk + bKo]);
                LDMATRIX_X4(bl[p][0], bl[p][1], bl[p][2], bl[p][3], adr);
            }
            #pragma unroll
            for (int mi = 0; mi < 2; mi++) {
                #pragma unroll
                for (int ni = 0; ni < 8; ni++) {
                    const int p = ni >> 1, sel = (ni & 1) * 2;
                    MMA_BF16(acc[mi][ni], ah[mi], bh[p][sel], bh[p][sel + 1]);
                    MMA_BF16(acc[mi][ni], ah[mi], bl[p][sel], bl[p][sel + 1]);
                    MMA_BF16(acc[mi][ni], al[mi], bh[p][sel], bh[p][sel + 1]);
                }
            }
        }
    }

    // ---- epilogue: bias + scatter to xp[d][s][b][h] ----
    #pragma unroll
    for (int mi = 0; mi < 2; mi++) {
        #pragma unroll
        for (int ni = 0; ni < 8; ni++) {
            const int n = nBase + warpN + ni * 8 + (lane & 3) * 2;
            const float bsum0 = bias1[n] + bias2[n];
            const float bsum1 = bias1[n + 1] + bias2[n + 1];
            const int d = n >> 9, h = n & 511;
            #pragma unroll
            for (int half = 0; half < 2; half++) {
                const int r = mBase + warpM + mi * 16 + (lane >> 2) + half * 8;
                const int s = r >> 6, b = r & 63;
                float2 o;
                o.x = acc[mi][ni][half * 2 + 0] + bsum0;
                o.y = acc[mi][ni][half * 2 + 1] + bsum1;
                *reinterpret_cast<float2*>(
                    xp + ((size_t)d * SEQL * BATCHN + (size_t)s * BATCHN + b) * HID + h) = o;
            }
        }
    }
}

// =====================================================================
// fp32 SIMT GEMM, f32x2 FMA (unchanged — used for gemm0 + fc)
// =====================================================================
template<int GATHER, int SCATTER, int NBIAS, int BN>
__global__ void __launch_bounds__(256, 2)
gemm_k(const float* __restrict__ A, const float* __restrict__ Bw,
       const float* __restrict__ bias1, const float* __restrict__ bias2,
       float* __restrict__ C,
       const int* __restrict__ gidx, const float* __restrict__ gtab,
       int N, int K, int nOff, int Nfull)
{
    constexpr int BM = 128, BK = 16;
    constexpr int COLS = BN / 16;
    constexpr int BF4  = BN / 64;
    __shared__ float As[2][BK][BM];
    __shared__ float Bs[2][BK][BN];

    const int tid   = threadIdx.x;
    const int mBase = blockIdx.y * BM;
    const int nBase = blockIdx.x * BN;
    const int tx = tid & 15;
    const int ty = tid >> 4;

    const int ar0 = tid >> 2;
    const int ak4 = (tid & 3) * 4;
    const int br  = (BN == 128) ? (tid >> 1) : (tid >> 2);
    const int bko = (BN == 128) ? ((tid & 1) * 8) : ((tid & 3) * 4);

    const int row0 = mBase + ar0;
    const int row1 = row0 + 64;
    const float* arp0;
    const float* arp1;
    if (GATHER) {
        arp0 = gtab + (size_t)gidx[row0] * K;
        arp1 = gtab + (size_t)gidx[row1] * K;
    } else {
        arp0 = A + (size_t)row0 * K;
        arp1 = A + (size_t)row1 * K;
    }
    const int brow = nBase + br;
    const float* brp = (brow < N) ? (Bw + (size_t)brow * K) : nullptr;

    const int KT = K / BK;
    float4 a0r, a1r, b0r[BF4];

    a0r = *reinterpret_cast<const float4*>(arp0 + ak4);
    a1r = *reinterpret_cast<const float4*>(arp1 + ak4);
    #pragma unroll
    for (int f = 0; f < BF4; f++)
        b0r[f] = brp ? *reinterpret_cast<const float4*>(brp + bko + 4 * f)
                     : make_float4(0.f, 0.f, 0.f, 0.f);
    {
        As[0][ak4+0][ar0]    = a0r.x; As[0][ak4+1][ar0]    = a0r.y;
        As[0][ak4+2][ar0]    = a0r.z; As[0][ak4+3][ar0]    = a0r.w;
        As[0][ak4+0][ar0+64] = a1r.x; As[0][ak4+1][ar0+64] = a1r.y;
        As[0][ak4+2][ar0+64] = a1r.z; As[0][ak4+3][ar0+64] = a1r.w;
        #pragma unroll
        for (int f = 0; f < BF4; f++) {
            Bs[0][bko+4*f+0][br] = b0r[f].x; Bs[0][bko+4*f+1][br] = b0r[f].y;
            Bs[0][bko+4*f+2][br] = b0r[f].z; Bs[0][bko+4*f+3][br] = b0r[f].w;
        }
    }
    __syncthreads();

    u64 acc2[4][COLS];
    #pragma unroll
    for (int i = 0; i < 4; i++)
        #pragma unroll
        for (int j = 0; j < COLS; j++) acc2[i][j] = 0ull;

    #pragma unroll 1
    for (int kt = 0; kt < KT; kt++) {
        const int buf = kt & 1;
        if (kt + 1 < KT) {
            const int ka = (kt + 1) * BK;
            a0r = *reinterpret_cast<const float4*>(arp0 + ka + ak4);
            a1r = *reinterpret_cast<const float4*>(arp1 + ka + ak4);
            #pragma unroll
            for (int f = 0; f < BF4; f++)
                b0r[f] = brp ? *reinterpret_cast<const float4*>(brp + ka + bko + 4 * f)
                             : make_float4(0.f, 0.f, 0.f, 0.f);
        }
        #pragma unroll
        for (int k = 0; k < BK; k++) {
            ulonglong2 aA = *reinterpret_cast<const ulonglong2*>(&As[buf][k][ty * 8]);
            ulonglong2 aB = *reinterpret_cast<const ulonglong2*>(&As[buf][k][ty * 8 + 4]);
            u64 a2[4] = {aA.x, aA.y, aB.x, aB.y};
            u64 b2[COLS];
            #pragma unroll
            for (int f = 0; f < BF4; f++) {
                float4 bf = *reinterpret_cast<const float4*>(&Bs[buf][k][tx * COLS + 4 * f]);
                b2[4*f+0] = pack2(bf.x, bf.x); b2[4*f+1] = pack2(bf.y, bf.y);
                b2[4*f+2] = pack2(bf.z, bf.z); b2[4*f+3] = pack2(bf.w, bf.w);
            }
            #pragma unroll
            for (int i = 0; i < 4; i++)
                #pragma unroll
                for (int j = 0; j < COLS; j++)
                    acc2[i][j] = ffma2(a2[i], b2[j], acc2[i][j]);
        }
        if (kt + 1 < KT) {
            const int nb = (kt + 1) & 1;
            As[nb][ak4+0][ar0]    = a0r.x; As[nb][ak4+1][ar0]    = a0r.y;
            As[nb][ak4+2][ar0]    = a0r.z; As[nb][ak4+3][ar0]    = a0r.w;
            As[nb][ak4+0][ar0+64] = a1r.x; As[nb][ak4+1][ar0+64] = a1r.y;
            As[nb][ak4+2][ar0+64] = a1r.z; As[nb][ak4+3][ar0+64] = a1r.w;
            #pragma unroll
            for (int f = 0; f < BF4; f++) {
                Bs[nb][bko+4*f+0][br] = b0r[f].x; Bs[nb][bko+4*f+1][br] = b0r[f].y;
                Bs[nb][bko+4*f+2][br] = b0r[f].z; Bs[nb][bko+4*f+3][br] = b0r[f].w;
            }
            __syncthreads();
        }
    }

    #pragma unroll
    for (int i2 = 0; i2 < 4; i2++) {
        #pragma unroll
        for (int j = 0; j < COLS; j++) {
            const int n = tx * COLS + j;
            if (nBase + n >= N) continue;
            const int nglob = nBase + n + nOff;
            float2 v2 = unpk2(acc2[i2][j]);
            float bsum = 0.f;
            if (NBIAS >= 1) bsum += bias1[nglob];
            if (NBIAS >= 2) bsum += bias2[nglob];
            #pragma unroll
            for (int half = 0; half < 2; half++) {
                const int m = mBase + ty * 8 + i2 * 2 + half;
                float v = (half ? v2.y : v2.x) + bsum;
                if (SCATTER) {
                    const int s = m >> 6, b = m & 63, d = nglob >> 9, h = nglob & 511;
                    C[(size_t)d * (SEQL * BATCHN * HID) +
                      (size_t)s * (BATCHN * HID) + b * HID + h] = v;
                } else {
                    C[(size_t)m * Nfull + nglob] = v;
                }
            }
        }
    }
}

// =====================================================================
// Recurrence (EXACT round-5 form — best measured: 1431us/launch)
// =====================================================================
__global__ void __cluster_dims__(8, 1, 1) __launch_bounds__(256, 1)
rnn_k(const float* __restrict__ xp, const float* __restrict__ whh,
      float* __restrict__ hout)
{
    const int r   = blockIdx.x & 7;
    const int cid = blockIdx.x >> 3;
    const int d   = cid & 1;
    const int g   = cid >> 1;
    const int t   = threadIdx.x;
    const int w   = t >> 5;
    const int oo  = t & 31;
    const int o0  = r * 64 + oo;
    const int o1  = o0 + 32;
    const int ck  = w * 64;

    u64 Wp0[32], Wp1[32];
    {
        const float* w0 = whh + (size_t)(d * HID + o0) * HID + ck;
        const float* w1 = whh + (size_t)(d * HID + o1) * HID + ck;
        #pragma unroll
        for (int i = 0; i < 16; i++) {
            ulonglong2 v0 = *reinterpret_cast<const ulonglong2*>(w0 + 4 * i);
            Wp0[2 * i] = v0.x; Wp0[2 * i + 1] = v0.y;
            ulonglong2 v1 = *reinterpret_cast<const ulonglong2*>(w1 + 4 * i);
            Wp1[2 * i] = v1.x; Wp1[2 * i + 1] = v1.y;
        }
    }

    float* sc0 = &g_hsc[0][d][g * 8][0];
    for (int i = t * 4; i < 4096; i += 1024)
        *reinterpret_cast<float4*>(sc0 + i) = make_float4(0.f, 0.f, 0.f, 0.f);

    asm volatile("barrier.cluster.arrive.aligned;" ::: "memory");
    asm volatile("barrier.cluster.wait.aligned;"   ::: "memory");

    __shared__ float h_sm[8][HID];
    __shared__ float part[8][64][12];

    const int ol  = t >> 2;
    const int b0  = (t & 3) * 2;
    const int orF = r * 64 + ol;
    const int gb0 = g * 8 + b0;

    float xv0, xv1;
    {
        const int s0 = d ? (SEQL - 1) : 0;
        const float* xpb = xp + ((size_t)(d * SEQL + s0) * BATCHN) * HID;
        xv0 = xpb[(size_t)gb0 * HID + orF];
        xv1 = xpb[(size_t)(gb0 + 1) * HID + orF];
    }

    #pragma unroll 1
    for (int step = 0; step < SEQL; step++) {
        const int s = d ? (SEQL - 1 - step) : step;
        {
            const float* base = &g_hsc[step & 1][d][g * 8][0];
            #pragma unroll
            for (int j = 0; j < 4; j++) {
                const int flat = j * 32 + oo;
                const int b  = flat >> 4;
                const int kk = (flat & 15) * 4;
                float4 v = __ldcg(reinterpret_cast<const float4*>(
                                  base + (size_t)b * HID + ck + kk));
                *reinterpret_cast<float4*>(&h_sm[b][ck + kk]) = v;
            }
        }
        __syncwarp();

        u64 a0[8], a1[8];
        #pragma unroll
        for (int b = 0; b < 8; b++) { a0[b] = 0ull; a1[b] = 0ull; }
        #pragma unroll
        for (int i = 0; i < 16; i++) {
            #pragma unroll
            for (int b = 0; b < 8; b++) {
                ulonglong2 hv = *reinterpret_cast<const ulonglong2*>(&h_sm[b][ck + 4 * i]);
                a0[b] = ffma2(Wp0[2 * i],     hv.x, a0[b]);
                a0[b] = ffma2(Wp0[2 * i + 1], hv.y, a0[b]);
                a1[b] = ffma2(Wp1[2 * i],     hv.x, a1[b]);
                a1[b] = ffma2(Wp1[2 * i + 1], hv.y, a1[b]);
            }
        }
        {
            float p[8], q[8];
            #pragma unroll
            for (int b = 0; b < 8; b++) {
                float2 f0 = unpk2(a0[b]); p[b] = f0.x + f0.y;
                float2 f1 = unpk2(a1[b]); q[b] = f1.x + f1.y;
            }
            *reinterpret_cast<float4*>(&part[w][oo][0])      = make_float4(p[0], p[1], p[2], p[3]);
            *reinterpret_cast<float4*>(&part[w][oo][4])      = make_float4(p[4], p[5], p[6], p[7]);
            *reinterpret_cast<float4*>(&part[w][oo + 32][0]) = make_float4(q[0], q[1], q[2], q[3]);
            *reinterpret_cast<float4*>(&part[w][oo + 32][4]) = make_float4(q[4], q[5], q[6], q[7]);
        }
        __syncthreads();

        float v0 = xv0, v1 = xv1;
        #pragma unroll
        for (int c = 0; c < 8; c++) {
            float2 pv = *reinterpret_cast<const float2*>(&part[c][ol][b0]);
            v0 += pv.x; v1 += pv.y;
        }
        v0 = fmaxf(v0, 0.f);
        v1 = fmaxf(v1, 0.f);
        float* scn = &g_hsc[(step + 1) & 1][d][0][0];
        __stcg(&scn[(size_t)gb0 * HID + orF], v0);
        __stcg(&scn[(size_t)(gb0 + 1) * HID + orF], v1);

        asm volatile("barrier.cluster.arrive.aligned;" ::: "memory");
        {
            float* ho = hout + ((size_t)s * BATCHN + gb0) * (2 * HID) + d * HID + orF;
            ho[0]       = v0;
            ho[2 * HID] = v1;
        }
        if (step + 1 < SEQL) {
            const int sn = d ? (SEQL - 2 - step) : (step + 1);
            const float* xpb = xp + ((size_t)(d * SEQL + sn) * BATCHN) * HID;
            xv0 = xpb[(size_t)gb0 * HID + orF];
            xv1 = xpb[(size_t)(gb0 + 1) * HID + orF];
        }
        asm volatile("barrier.cluster.wait.aligned;" ::: "memory");
    }
}

// =====================================================================
extern "C" void kernel_launch(void* const* d_in, const int* in_sizes, int n_in,
                              void* d_out, int out_size)
{
    const int*   text   = (const int*)  d_in[0];
    const float* emb    = (const float*)d_in[1];
    const float* emfc_w = (const float*)d_in[2];
    const float* emfc_b = (const float*)d_in[3];
    const float* w_ih0  = (const float*)d_in[4];
    const float* w_hh0  = (const float*)d_in[5];
    const float* b_ih0  = (const float*)d_in[6];
    const float* b_hh0  = (const float*)d_in[7];
    const float* w_ih1  = (const float*)d_in[8];
    const float* w_hh1  = (const float*)d_in[9];
    const float* b_ih1  = (const float*)d_in[10];
    const float* b_hh1  = (const float*)d_in[11];
    const float* fc_w   = (const float*)d_in[12];
    const float* fc_b   = (const float*)d_in[13];
    float* out = (float*)d_out;

    float *p_pe, *p_xp0, *p_h0, *p_xp1, *p_h1;
    __nv_bfloat16 *p_wh0, *p_wl0, *p_wh1, *p_wl1;
    cudaGetSymbolAddress((void**)&p_pe,  g_post_emb);
    cudaGetSymbolAddress((void**)&p_xp0, g_xp0);
    cudaGetSymbolAddress((void**)&p_h0,  g_h0);
    cudaGetSymbolAddress((void**)&p_xp1, g_xp1);
    cudaGetSymbolAddress((void**)&p_h1,  g_h1);
    cudaGetSymbolAddress((void**)&p_wh0, g_wh0);
    cudaGetSymbolAddress((void**)&p_wl0, g_wl0);
    cudaGetSymbolAddress((void**)&p_wh1, g_wh1);
    cudaGetSymbolAddress((void**)&p_wl1, g_wl1);

    dim3 blk(256);

    // 0-1) weight hi/lo splits
    wconv_k<<<(1024 * EMBD) / 256, 256>>>(w_ih0, p_wh0, p_wl0, 1024 * EMBD);
    wconv_k<<<(1024 * 1024) / 256, 256>>>(w_ih1, p_wh1, p_wl1, 1024 * 1024);

    // 2) post_emb = gather(emb, text) @ emfc_w^T + emfc_b   (SIMT, gather once)
    gemm_k<1,0,1,128><<<dim3(EMBD/128, MROWS/128), blk>>>(
        nullptr, emfc_w, emfc_b, nullptr, p_pe, text, emb, EMBD, EMBD, 0, EMBD);

    // 3) xp0 = post_emb @ w_ih0^T + b  (mma.sync split-bf16, K=256)
    mma_xp_k<<<dim3(8, 128), blk>>>(p_pe, EMBD, p_wh0, p_wl0, b_ih0, b_hh0, p_xp0);

    // 4) layer-0 recurrence -> h0
    rnn_k<<<128, blk>>>(p_xp0, w_hh0, p_h0);

    // 5) xp1 = h0 @ w_ih1^T + b  (mma.sync split-bf16, K=1024)  [ncu index 5]
    mma_xp_k<<<dim3(8, 128), blk>>>(p_h0, 1024, p_wh1, p_wl1, b_ih1, b_hh1, p_xp1);

    // 6) layer-1 recurrence -> h1
    rnn_k<<<128, blk>>>(p_xp1, w_hh1, p_h1);

    // 7) out = h1 @ fc_w^T + fc_b   (SIMT)
    gemm_k<0,0,1,64><<<dim3(1, MROWS/128), blk>>>(
        p_h1, fc_w, fc_b, nullptr, out, nullptr, nullptr, OUTD, 1024, 0, OUTD);
}

// round 17
// speedup vs baseline: 1.7820x; 1.0069x over previous
#include <cuda_runtime.h>
#include <cuda_bf16.h>
#include <cstdint>

#define SEQL  256
#define BATCHN 64
#define EMBD  256
#define HID   512
#define OUTD  18
#define MROWS (SEQL*BATCHN)   // 16384

typedef unsigned long long u64;

// ---------------- packed f32x2 helpers ----------------
__device__ __forceinline__ u64 ffma2(u64 a, u64 b, u64 c) {
    u64 d; asm("fma.rn.f32x2 %0, %1, %2, %3;" : "=l"(d) : "l"(a), "l"(b), "l"(c));
    return d;
}
__device__ __forceinline__ u64 pack2(float lo, float hi) {
    u64 r; asm("mov.b64 %0, {%1, %2};" : "=l"(r) : "f"(lo), "f"(hi));
    return r;
}
__device__ __forceinline__ float2 unpk2(u64 v) {
    float lo, hi; asm("mov.b64 {%0, %1}, %2;" : "=f"(lo), "=f"(hi) : "l"(v));
    return make_float2(lo, hi);
}
__device__ __forceinline__ uint32_t smem_u32(const void* p) {
    uint32_t a;
    asm("{ .reg .u64 tt; cvta.to.shared.u64 tt, %1; cvt.u32.u64 %0, tt; }" : "=r"(a) : "l"(p));
    return a;
}

// ---------------- mma.sync / ldmatrix (baseline PTX, sm_80+) ----------------
#define LDMATRIX_X4(r0, r1, r2, r3, addr) \
    asm volatile("ldmatrix.sync.aligned.m8n8.x4.shared.b16 {%0,%1,%2,%3}, [%4];" \
        : "=r"(r0), "=r"(r1), "=r"(r2), "=r"(r3) : "r"(addr))

#define MMA_BF16(c, a, b0v, b1v) \
    asm volatile("mma.sync.aligned.m16n8k16.row.col.f32.bf16.bf16.f32 " \
        "{%0,%1,%2,%3}, {%4,%5,%6,%7}, {%8,%9}, {%0,%1,%2,%3};" \
        : "+f"((c)[0]), "+f"((c)[1]), "+f"((c)[2]), "+f"((c)[3]) \
        : "r"((a)[0]), "r"((a)[1]), "r"((a)[2]), "r"((a)[3]), "r"(b0v), "r"(b1v))

// ---------------- scratch (static device arrays; no allocation) ----------------
__device__ float g_post_emb[MROWS * EMBD];            // 16 MB
__device__ float g_xp0[2 * SEQL * BATCHN * HID];      // 64 MB  [d][s][b][h]
__device__ float g_h0 [MROWS * 2 * HID];              // 64 MB  [s][b][2H]
__device__ float g_xp1[2 * SEQL * BATCHN * HID];      // 64 MB
__device__ float g_h1 [MROWS * 2 * HID];              // 64 MB
__device__ float g_hsc[2][2][BATCHN][HID];            // 512 KB [buf][dir][b][h]
__device__ __nv_bfloat16 g_wh0[1024 * EMBD];          // w_ih0 hi
__device__ __nv_bfloat16 g_wl0[1024 * EMBD];          // w_ih0 lo
__device__ __nv_bfloat16 g_wh1[1024 * 1024];          // w_ih1 hi
__device__ __nv_bfloat16 g_wl1[1024 * 1024];          // w_ih1 lo
__device__ __nv_bfloat16 g_whE[EMBD * EMBD];          // emfc_w hi
__device__ __nv_bfloat16 g_wlE[EMBD * EMBD];          // emfc_w lo

// =====================================================================
// weight split: fp32 -> bf16 hi + bf16 lo
// =====================================================================
__global__ void wconv_k(const float* __restrict__ w,
                        __nv_bfloat16* __restrict__ wh,
                        __nv_bfloat16* __restrict__ wl, int n)
{
    int i = blockIdx.x * 256 + threadIdx.x;
    if (i < n) {
        float x = w[i];
        __nv_bfloat16 h = __float2bfloat16(x);
        wh[i] = h;
        wl[i] = __float2bfloat16(x - __bfloat162float(h));
    }
}

// =====================================================================
// split-bf16 3-pass mma.sync GEMM:
//   C = A[16384,K] @ W[N,K]^T + bias   (N multiple of 128)
// CTA tile 128x128, warp tile 32x64, BK=32, 8 warps.
// GATHER: A row m = gtab[gidx[m]*K ...]  (fp32, converted hi/lo inline)
// SCATTER: write to xp[d][s][b][h]; else C[m*Nfull + n].
// Passes: Ah*Bh + Ah*Bl + Al*Bh (AlBl ~4e-6, dropped).
// =====================================================================
#define TCS 40   // smem row stride in bf16

template<int GATHER, int SCATTER, int NBIAS>
__global__ void __launch_bounds__(256, 1)
mma_xp_k(const float* __restrict__ A, int K,
         const __nv_bfloat16* __restrict__ Wh, const __nv_bfloat16* __restrict__ Wl,
         const float* __restrict__ bias1, const float* __restrict__ bias2,
         float* __restrict__ xp,
         const int* __restrict__ gidx, const float* __restrict__ gtab, int Nfull)
{
    __shared__ __nv_bfloat16 Ah[128][TCS], Al[128][TCS];
    __shared__ __nv_bfloat16 Bh[128][TCS], Bl[128][TCS];

    const int tid  = threadIdx.x;
    const int wid  = tid >> 5;
    const int lane = tid & 31;
    const int nBase = blockIdx.x * 128;
    const int mBase = blockIdx.y * 128;
    const int warpM = (wid >> 1) * 32;   // 4 warps over M
    const int warpN = (wid & 1) * 64;    // 2 warps over N

    // staging assignment: row = tid>>1 (0..127), half = tid&1 (k 0-15 / 16-31)
    const int srow  = tid >> 1;
    const int shalf = (tid & 1) * 16;
    const float* arow;
    if (GATHER) arow = gtab + (size_t)gidx[mBase + srow] * K + shalf;
    else        arow = A + (size_t)(mBase + srow) * K + shalf;
    const __nv_bfloat16* whrow = Wh + (size_t)(nBase + srow) * K + shalf;
    const __nv_bfloat16* wlrow = Wl + (size_t)(nBase + srow) * K + shalf;

    // ldmatrix source addresses (canonical m16n8k16 fragment layouts)
    const int aRow = lane & 15;
    const int aKo  = (lane >> 4) << 3;
    const int bRow = (lane & 7) + ((lane >> 4) << 3);
    const int bKo  = ((lane >> 3) & 1) << 3;

    float acc[2][8][4];
    #pragma unroll
    for (int mi = 0; mi < 2; mi++)
        #pragma unroll
        for (int ni = 0; ni < 8; ni++)
            #pragma unroll
            for (int c = 0; c < 4; c++) acc[mi][ni][c] = 0.f;

    const int nkc = K >> 5;
    #pragma unroll 1
    for (int kc = 0; kc < nkc; kc++) {
        __syncthreads();
        // ---- stage A (fp32 -> hi/lo bf16) ----
        {
            const float* ap = arow + kc * 32;
            float4 v0 = *reinterpret_cast<const float4*>(ap);
            float4 v1 = *reinterpret_cast<const float4*>(ap + 4);
            float4 v2 = *reinterpret_cast<const float4*>(ap + 8);
            float4 v3 = *reinterpret_cast<const float4*>(ap + 12);
            float vv[16] = {v0.x,v0.y,v0.z,v0.w, v1.x,v1.y,v1.z,v1.w,
                            v2.x,v2.y,v2.z,v2.w, v3.x,v3.y,v3.z,v3.w};
            __nv_bfloat16 hh[16], ll[16];
            #pragma unroll
            for (int i = 0; i < 16; i++) {
                hh[i] = __float2bfloat16(vv[i]);
                ll[i] = __float2bfloat16(vv[i] - __bfloat162float(hh[i]));
            }
            *reinterpret_cast<uint4*>(&Ah[srow][shalf])     = *reinterpret_cast<uint4*>(&hh[0]);
            *reinterpret_cast<uint4*>(&Ah[srow][shalf + 8]) = *reinterpret_cast<uint4*>(&hh[8]);
            *reinterpret_cast<uint4*>(&Al[srow][shalf])     = *reinterpret_cast<uint4*>(&ll[0]);
            *reinterpret_cast<uint4*>(&Al[srow][shalf + 8]) = *reinterpret_cast<uint4*>(&ll[8]);
        }
        // ---- stage B (pre-split bf16) ----
        {
            const __nv_bfloat16* bh = whrow + kc * 32;
            const __nv_bfloat16* bl = wlrow + kc * 32;
            uint4 h0 = *reinterpret_cast<const uint4*>(bh);
            uint4 h1 = *reinterpret_cast<const uint4*>(bh + 8);
            uint4 l0 = *reinterpret_cast<const uint4*>(bl);
            uint4 l1 = *reinterpret_cast<const uint4*>(bl + 8);
            *reinterpret_cast<uint4*>(&Bh[srow][shalf])     = h0;
            *reinterpret_cast<uint4*>(&Bh[srow][shalf + 8]) = h1;
            *reinterpret_cast<uint4*>(&Bl[srow][shalf])     = l0;
            *reinterpret_cast<uint4*>(&Bl[srow][shalf + 8]) = l1;
        }
        __syncthreads();

        // ---- compute: 2 k-steps of 16 ----
        #pragma unroll
        for (int ks = 0; ks < 2; ks++) {
            const int kk = ks * 16;
            uint32_t ah[2][4], al[2][4];
            #pragma unroll
            for (int mi = 0; mi < 2; mi++) {
                uint32_t adr = smem_u32(&Ah[warpM + mi * 16 + aRow][kk + aKo]);
                LDMATRIX_X4(ah[mi][0], ah[mi][1], ah[mi][2], ah[mi][3], adr);
                adr = smem_u32(&Al[warpM + mi * 16 + aRow][kk + aKo]);
                LDMATRIX_X4(al[mi][0], al[mi][1], al[mi][2], al[mi][3], adr);
            }
            uint32_t bh[4][4], bl[4][4];
            #pragma unroll
            for (int p = 0; p < 4; p++) {
                uint32_t adr = smem_u32(&Bh[warpN + p * 16 + bRow][kk + bKo]);
                LDMATRIX_X4(bh[p][0], bh[p][1], bh[p][2], bh[p][3], adr);
                adr = smem_u32(&Bl[warpN + p * 16 + bRow][kk + bKo]);
                LDMATRIX_X4(bl[p][0], bl[p][1], bl[p][2], bl[p][3], adr);
            }
            #pragma unroll
            for (int mi = 0; mi < 2; mi++) {
                #pragma unroll
                for (int ni = 0; ni < 8; ni++) {
                    const int p = ni >> 1, sel = (ni & 1) * 2;
                    MMA_BF16(acc[mi][ni], ah[mi], bh[p][sel], bh[p][sel + 1]);
                    MMA_BF16(acc[mi][ni], ah[mi], bl[p][sel], bl[p][sel + 1]);
                    MMA_BF16(acc[mi][ni], al[mi], bh[p][sel], bh[p][sel + 1]);
                }
            }
        }
    }

    // ---- epilogue: bias + store ----
    #pragma unroll
    for (int mi = 0; mi < 2; mi++) {
        #pragma unroll
        for (int ni = 0; ni < 8; ni++) {
            const int n = nBase + warpN + ni * 8 + (lane & 3) * 2;
            float bsum0 = 0.f, bsum1 = 0.f;
            if (NBIAS >= 1) { bsum0 += bias1[n]; bsum1 += bias1[n + 1]; }
            if (NBIAS >= 2) { bsum0 += bias2[n]; bsum1 += bias2[n + 1]; }
            #pragma unroll
            for (int half = 0; half < 2; half++) {
                const int r = mBase + warpM + mi * 16 + (lane >> 2) + half * 8;
                float2 o;
                o.x = acc[mi][ni][half * 2 + 0] + bsum0;
                o.y = acc[mi][ni][half * 2 + 1] + bsum1;
                if (SCATTER) {
                    const int d = n >> 9, h = n & 511;
                    const int s = r >> 6, b = r & 63;
                    *reinterpret_cast<float2*>(
                        xp + ((size_t)d * SEQL * BATCHN + (size_t)s * BATCHN + b) * HID + h) = o;
                } else {
                    *reinterpret_cast<float2*>(xp + (size_t)r * Nfull + n) = o;
                }
            }
        }
    }
}

// =====================================================================
// fp32 SIMT GEMM, f32x2 FMA (kept for the small fc GEMM)
// =====================================================================
template<int GATHER, int SCATTER, int NBIAS, int BN>
__global__ void __launch_bounds__(256, 2)
gemm_k(const float* __restrict__ A, const float* __restrict__ Bw,
       const float* __restrict__ bias1, const float* __restrict__ bias2,
       float* __restrict__ C,
       const int* __restrict__ gidx, const float* __restrict__ gtab,
       int N, int K, int nOff, int Nfull)
{
    constexpr int BM = 128, BK = 16;
    constexpr int COLS = BN / 16;
    constexpr int BF4  = BN / 64;
    __shared__ float As[2][BK][BM];
    __shared__ float Bs[2][BK][BN];

    const int tid   = threadIdx.x;
    const int mBase = blockIdx.y * BM;
    const int nBase = blockIdx.x * BN;
    const int tx = tid & 15;
    const int ty = tid >> 4;

    const int ar0 = tid >> 2;
    const int ak4 = (tid & 3) * 4;
    const int br  = (BN == 128) ? (tid >> 1) : (tid >> 2);
    const int bko = (BN == 128) ? ((tid & 1) * 8) : ((tid & 3) * 4);

    const int row0 = mBase + ar0;
    const int row1 = row0 + 64;
    const float* arp0;
    const float* arp1;
    if (GATHER) {
        arp0 = gtab + (size_t)gidx[row0] * K;
        arp1 = gtab + (size_t)gidx[row1] * K;
    } else {
        arp0 = A + (size_t)row0 * K;
        arp1 = A + (size_t)row1 * K;
    }
    const int brow = nBase + br;
    const float* brp = (brow < N) ? (Bw + (size_t)brow * K) : nullptr;

    const int KT = K / BK;
    float4 a0r, a1r, b0r[BF4];

    a0r = *reinterpret_cast<const float4*>(arp0 + ak4);
    a1r = *reinterpret_cast<const float4*>(arp1 + ak4);
    #pragma unroll
    for (int f = 0; f < BF4; f++)
        b0r[f] = brp ? *reinterpret_cast<const float4*>(brp + bko + 4 * f)
                     : make_float4(0.f, 0.f, 0.f, 0.f);
    {
        As[0][ak4+0][ar0]    = a0r.x; As[0][ak4+1][ar0]    = a0r.y;
        As[0][ak4+2][ar0]    = a0r.z; As[0][ak4+3][ar0]    = a0r.w;
        As[0][ak4+0][ar0+64] = a1r.x; As[0][ak4+1][ar0+64] = a1r.y;
        As[0][ak4+2][ar0+64] = a1r.z; As[0][ak4+3][ar0+64] = a1r.w;
        #pragma unroll
        for (int f = 0; f < BF4; f++) {
            Bs[0][bko+4*f+0][br] = b0r[f].x; Bs[0][bko+4*f+1][br] = b0r[f].y;
            Bs[0][bko+4*f+2][br] = b0r[f].z; Bs[0][bko+4*f+3][br] = b0r[f].w;
        }
    }
    __syncthreads();

    u64 acc2[4][COLS];
    #pragma unroll
    for (int i = 0; i < 4; i++)
        #pragma unroll
        for (int j = 0; j < COLS; j++) acc2[i][j] = 0ull;

    #pragma unroll 1
    for (int kt = 0; kt < KT; kt++) {
        const int buf = kt & 1;
        if (kt + 1 < KT) {
            const int ka = (kt + 1) * BK;
            a0r = *reinterpret_cast<const float4*>(arp0 + ka + ak4);
            a1r = *reinterpret_cast<const float4*>(arp1 + ka + ak4);
            #pragma unroll
            for (int f = 0; f < BF4; f++)
                b0r[f] = brp ? *reinterpret_cast<const float4*>(brp + ka + bko + 4 * f)
                             : make_float4(0.f, 0.f, 0.f, 0.f);
        }
        #pragma unroll
        for (int k = 0; k < BK; k++) {
            ulonglong2 aA = *reinterpret_cast<const ulonglong2*>(&As[buf][k][ty * 8]);
            ulonglong2 aB = *reinterpret_cast<const ulonglong2*>(&As[buf][k][ty * 8 + 4]);
            u64 a2[4] = {aA.x, aA.y, aB.x, aB.y};
            u64 b2[COLS];
            #pragma unroll
            for (int f = 0; f < BF4; f++) {
                float4 bf = *reinterpret_cast<const float4*>(&Bs[buf][k][tx * COLS + 4 * f]);
                b2[4*f+0] = pack2(bf.x, bf.x); b2[4*f+1] = pack2(bf.y, bf.y);
                b2[4*f+2] = pack2(bf.z, bf.z); b2[4*f+3] = pack2(bf.w, bf.w);
            }
            #pragma unroll
            for (int i = 0; i < 4; i++)
                #pragma unroll
                for (int j = 0; j < COLS; j++)
                    acc2[i][j] = ffma2(a2[i], b2[j], acc2[i][j]);
        }
        if (kt + 1 < KT) {
            const int nb = (kt + 1) & 1;
            As[nb][ak4+0][ar0]    = a0r.x; As[nb][ak4+1][ar0]    = a0r.y;
            As[nb][ak4+2][ar0]    = a0r.z; As[nb][ak4+3][ar0]    = a0r.w;
            As[nb][ak4+0][ar0+64] = a1r.x; As[nb][ak4+1][ar0+64] = a1r.y;
            As[nb][ak4+2][ar0+64] = a1r.z; As[nb][ak4+3][ar0+64] = a1r.w;
            #pragma unroll
            for (int f = 0; f < BF4; f++) {
                Bs[nb][bko+4*f+0][br] = b0r[f].x; Bs[nb][bko+4*f+1][br] = b0r[f].y;
                Bs[nb][bko+4*f+2][br] = b0r[f].z; Bs[nb][bko+4*f+3][br] = b0r[f].w;
            }
            __syncthreads();
        }
    }

    #pragma unroll
    for (int i2 = 0; i2 < 4; i2++) {
        #pragma unroll
        for (int j = 0; j < COLS; j++) {
            const int n = tx * COLS + j;
            if (nBase + n >= N) continue;
            const int nglob = nBase + n + nOff;
            float2 v2 = unpk2(acc2[i2][j]);
            float bsum = 0.f;
            if (NBIAS >= 1) bsum += bias1[nglob];
            if (NBIAS >= 2) bsum += bias2[nglob];
            #pragma unroll
            for (int half = 0; half < 2; half++) {
                const int m = mBase + ty * 8 + i2 * 2 + half;
                float v = (half ? v2.y : v2.x) + bsum;
                if (SCATTER) {
                    const int s = m >> 6, b = m & 63, d = nglob >> 9, h = nglob & 511;
                    C[(size_t)d * (SEQL * BATCHN * HID) +
                      (size_t)s * (BATCHN * HID) + b * HID + h] = v;
                } else {
                    C[(size_t)m * Nfull + nglob] = v;
                }
            }
        }
    }
}

// =====================================================================
// Recurrence (EXACT round-5 form — best measured: 1431us/launch)
// =====================================================================
__global__ void __cluster_dims__(8, 1, 1) __launch_bounds__(256, 1)
rnn_k(const float* __restrict__ xp, const float* __restrict__ whh,
      float* __restrict__ hout)
{
    const int r   = blockIdx.x & 7;
    const int cid = blockIdx.x >> 3;
    const int d   = cid & 1;
    const int g   = cid >> 1;
    const int t   = threadIdx.x;
    const int w   = t >> 5;
    const int oo  = t & 31;
    const int o0  = r * 64 + oo;
    const int o1  = o0 + 32;
    const int ck  = w * 64;

    u64 Wp0[32], Wp1[32];
    {
        const float* w0 = whh + (size_t)(d * HID + o0) * HID + ck;
        const float* w1 = whh + (size_t)(d * HID + o1) * HID + ck;
        #pragma unroll
        for (int i = 0; i < 16; i++) {
            ulonglong2 v0 = *reinterpret_cast<const ulonglong2*>(w0 + 4 * i);
            Wp0[2 * i] = v0.x; Wp0[2 * i + 1] = v0.y;
            ulonglong2 v1 = *reinterpret_cast<const ulonglong2*>(w1 + 4 * i);
            Wp1[2 * i] = v1.x; Wp1[2 * i + 1] = v1.y;
        }
    }

    float* sc0 = &g_hsc[0][d][g * 8][0];
    for (int i = t * 4; i < 4096; i += 1024)
        *reinterpret_cast<float4*>(sc0 + i) = make_float4(0.f, 0.f, 0.f, 0.f);

    asm volatile("barrier.cluster.arrive.aligned;" ::: "memory");
    asm volatile("barrier.cluster.wait.aligned;"   ::: "memory");

    __shared__ float h_sm[8][HID];
    __shared__ float part[8][64][12];

    const int ol  = t >> 2;
    const int b0  = (t & 3) * 2;
    const int orF = r * 64 + ol;
    const int gb0 = g * 8 + b0;

    float xv0, xv1;
    {
        const int s0 = d ? (SEQL - 1) : 0;
        const float* xpb = xp + ((size_t)(d * SEQL + s0) * BATCHN) * HID;
        xv0 = xpb[(size_t)gb0 * HID + orF];
        xv1 = xpb[(size_t)(gb0 + 1) * HID + orF];
    }

    #pragma unroll 1
    for (int step = 0; step < SEQL; step++) {
        const int s = d ? (SEQL - 1 - step) : step;
        {
            const float* base = &g_hsc[step & 1][d][g * 8][0];
            #pragma unroll
            for (int j = 0; j < 4; j++) {
                const int flat = j * 32 + oo;
                const int b  = flat >> 4;
                const int kk = (flat & 15) * 4;
                float4 v = __ldcg(reinterpret_cast<const float4*>(
                                  base + (size_t)b * HID + ck + kk));
                *reinterpret_cast<float4*>(&h_sm[b][ck + kk]) = v;
            }
        }
        __syncwarp();

        u64 a0[8], a1[8];
        #pragma unroll
        for (int b = 0; b < 8; b++) { a0[b] = 0ull; a1[b] = 0ull; }
        #pragma unroll
        for (int i = 0; i < 16; i++) {
            #pragma unroll
            for (int b = 0; b < 8; b++) {
                ulonglong2 hv = *reinterpret_cast<const ulonglong2*>(&h_sm[b][ck + 4 * i]);
                a0[b] = ffma2(Wp0[2 * i],     hv.x, a0[b]);
                a0[b] = ffma2(Wp0[2 * i + 1], hv.y, a0[b]);
                a1[b] = ffma2(Wp1[2 * i],     hv.x, a1[b]);
                a1[b] = ffma2(Wp1[2 * i + 1], hv.y, a1[b]);
            }
        }
        {
            float p[8], q[8];
            #pragma unroll
            for (int b = 0; b < 8; b++) {
                float2 f0 = unpk2(a0[b]); p[b] = f0.x + f0.y;
                float2 f1 = unpk2(a1[b]); q[b] = f1.x + f1.y;
            }
            *reinterpret_cast<float4*>(&part[w][oo][0])      = make_float4(p[0], p[1], p[2], p[3]);
            *reinterpret_cast<float4*>(&part[w][oo][4])      = make_float4(p[4], p[5], p[6], p[7]);
            *reinterpret_cast<float4*>(&part[w][oo + 32][0]) = make_float4(q[0], q[1], q[2], q[3]);
            *reinterpret_cast<float4*>(&part[w][oo + 32][4]) = make_float4(q[4], q[5], q[6], q[7]);
        }
        __syncthreads();

        float v0 = xv0, v1 = xv1;
        #pragma unroll
        for (int c = 0; c < 8; c++) {
            float2 pv = *reinterpret_cast<const float2*>(&part[c][ol][b0]);
            v0 += pv.x; v1 += pv.y;
        }
        v0 = fmaxf(v0, 0.f);
        v1 = fmaxf(v1, 0.f);
        float* scn = &g_hsc[(step + 1) & 1][d][0][0];
        __stcg(&scn[(size_t)gb0 * HID + orF], v0);
        __stcg(&scn[(size_t)(gb0 + 1) * HID + orF], v1);

        asm volatile("barrier.cluster.arrive.aligned;" ::: "memory");
        {
            float* ho = hout + ((size_t)s * BATCHN + gb0) * (2 * HID) + d * HID + orF;
            ho[0]       = v0;
            ho[2 * HID] = v1;
        }
        if (step + 1 < SEQL) {
            const int sn = d ? (SEQL - 2 - step) : (step + 1);
            const float* xpb = xp + ((size_t)(d * SEQL + sn) * BATCHN) * HID;
            xv0 = xpb[(size_t)gb0 * HID + orF];
            xv1 = xpb[(size_t)(gb0 + 1) * HID + orF];
        }
        asm volatile("barrier.cluster.wait.aligned;" ::: "memory");
    }
}

// =====================================================================
extern "C" void kernel_launch(void* const* d_in, const int* in_sizes, int n_in,
                              void* d_out, int out_size)
{
    const int*   text   = (const int*)  d_in[0];
    const float* emb    = (const float*)d_in[1];
    const float* emfc_w = (const float*)d_in[2];
    const float* emfc_b = (const float*)d_in[3];
    const float* w_ih0  = (const float*)d_in[4];
    const float* w_hh0  = (const float*)d_in[5];
    const float* b_ih0  = (const float*)d_in[6];
    const float* b_hh0  = (const float*)d_in[7];
    const float* w_ih1  = (const float*)d_in[8];
    const float* w_hh1  = (const float*)d_in[9];
    const float* b_ih1  = (const float*)d_in[10];
    const float* b_hh1  = (const float*)d_in[11];
    const float* fc_w   = (const float*)d_in[12];
    const float* fc_b   = (const float*)d_in[13];
    float* out = (float*)d_out;

    float *p_pe, *p_xp0, *p_h0, *p_xp1, *p_h1;
    __nv_bfloat16 *p_wh0, *p_wl0, *p_wh1, *p_wl1, *p_whE, *p_wlE;
    cudaGetSymbolAddress((void**)&p_pe,  g_post_emb);
    cudaGetSymbolAddress((void**)&p_xp0, g_xp0);
    cudaGetSymbolAddress((void**)&p_h0,  g_h0);
    cudaGetSymbolAddress((void**)&p_xp1, g_xp1);
    cudaGetSymbolAddress((void**)&p_h1,  g_h1);
    cudaGetSymbolAddress((void**)&p_wh0, g_wh0);
    cudaGetSymbolAddress((void**)&p_wl0, g_wl0);
    cudaGetSymbolAddress((void**)&p_wh1, g_wh1);
    cudaGetSymbolAddress((void**)&p_wl1, g_wl1);
    cudaGetSymbolAddress((void**)&p_whE, g_whE);
    cudaGetSymbolAddress((void**)&p_wlE, g_wlE);

    dim3 blk(256);

    // 0-2) weight hi/lo splits
    wconv_k<<<(EMBD * EMBD) / 256, 256>>>(emfc_w, p_whE, p_wlE, EMBD * EMBD);
    wconv_k<<<(1024 * EMBD) / 256, 256>>>(w_ih0, p_wh0, p_wl0, 1024 * EMBD);
    wconv_k<<<(1024 * 1024) / 256, 256>>>(w_ih1, p_wh1, p_wl1, 1024 * 1024);

    // 3) post_emb = gather(emb, text) @ emfc_w^T + emfc_b  (tensor, gather once)
    mma_xp_k<1,0,1><<<dim3(EMBD/128, MROWS/128), blk>>>(
        nullptr, EMBD, p_whE, p_wlE, emfc_b, nullptr, p_pe, text, emb, EMBD);

    // 4) xp0 = post_emb @ w_ih0^T + b  (tensor, K=256)
    mma_xp_k<0,1,2><<<dim3(8, 128), blk>>>(
        p_pe, EMBD, p_wh0, p_wl0, b_ih0, b_hh0, p_xp0, nullptr, nullptr, 0);

    // 5) layer-0 recurrence -> h0   [ncu index 5]
    rnn_k<<<128, blk>>>(p_xp0, w_hh0, p_h0);

    // 6) xp1 = h0 @ w_ih1^T + b  (tensor, K=1024)
    mma_xp_k<0,1,2><<<dim3(8, 128), blk>>>(
        p_h0, 1024, p_wh1, p_wl1, b_ih1, b_hh1, p_xp1, nullptr, nullptr, 0);

    // 7) layer-1 recurrence -> h1
    rnn_k<<<128, blk>>>(p_xp1, w_hh1, p_h1);

    // 8) out = h1 @ fc_w^T + fc_b   (SIMT)
    gemm_k<0,0,1,64><<<dim3(1, MROWS/128), blk>>>(
        p_h1, fc_w, fc_b, nullptr, out, nullptr, nullptr, OUTD, 1024, 0, OUTD);
}